// round 5
// baseline (speedup 1.0000x reference)
#include <cuda_runtime.h>
#include <cstdint>

#define BB 2
#define SQ 1024
#define SK 1024
#define DD 64
#define DV 64
#define NSPLIT 32
#define KCHUNK 32              // keys per block
#define KB 8                   // keys staged through hbuf per phase pass
#define QPB 128                // queries per block
#define TPB 128
#define NTILE (SQ / QPB)       // 8
#define NTAIL 4

#define LOG2E 1.4426950408889634f
#define ABS2_MASK 0x7FFFFFFF7FFFFFFFULL

typedef unsigned long long ull;

// partials: [b][split][dp(32)][q(1024)]
__device__ ull   g_pacc[(size_t)BB * NSPLIT * (DV / 2) * SQ];
__device__ float g_pl[(size_t)BB * NSPLIT * SQ];
__device__ int   g_cnt[BB * NTILE];
__device__ int   g_fin[BB * NTILE];

__device__ __forceinline__ ull add_f32x2(ull a, ull b) {
    ull r;
    asm("add.rn.f32x2 %0, %1, %2;" : "=l"(r) : "l"(a), "l"(b));
    return r;
}
__device__ __forceinline__ ull fma_f32x2(ull a, ull b, ull c) {
    ull r;
    asm("fma.rn.f32x2 %0, %1, %2, %3;" : "=l"(r) : "l"(a), "l"(b), "l"(c));
    return r;
}
__device__ __forceinline__ ull pack_dup(float p) {
    ull r;
    asm("mov.b64 %0, {%1, %1};" : "=l"(r) : "r"(__float_as_uint(p)));
    return r;
}
__device__ __forceinline__ float ex2(float x) {
    float r;
    asm("ex2.approx.f32 %0, %1;" : "=f"(r) : "f"(x));
    return r;
}

__global__ __launch_bounds__(TPB, 3)
void attn_fused(const float* __restrict__ q, const float* __restrict__ k,
                const float* __restrict__ v, const int* __restrict__ mask,
                float* __restrict__ out)
{
    const int b   = blockIdx.z;
    const int sg  = blockIdx.y;           // split 0..31
    const int qt  = blockIdx.x;           // q tile 0..7
    const int tid = threadIdx.x;
    const int g   = tid & 31;             // query group 0..31 (lane)
    const int c   = tid >> 5;             // dim quarter 0..3 (warp id)
    // this thread's 4 queries: qt*128 + g + 32*qq

    __shared__ __align__(16) float  ks[KCHUNK][DD];     // 8KB
    __shared__ __align__(16) float  vs[KCHUNK][DV];     // 8KB
    __shared__ __align__(16) float4 hbuf[KB][4][32];    // 16KB (quarter dists / p)
    __shared__ __align__(16) float  k0s[DD];
    __shared__ float bias[KCHUNK];
    __shared__ int   rank_s;

    // cooperative loads
    {
        const float* kb = k + ((size_t)b * SK + (size_t)sg * KCHUNK) * DD;
        const float* vb = v + ((size_t)b * SK + (size_t)sg * KCHUNK) * DV;
#pragma unroll
        for (int i = tid; i < KCHUNK * DD / 4; i += TPB) {
            ((float4*)&ks[0][0])[i] = ((const float4*)kb)[i];
            ((float4*)&vs[0][0])[i] = ((const float4*)vb)[i];
        }
        if (tid < KCHUNK)
            bias[tid] = mask[(size_t)b * SK + (size_t)sg * KCHUNK + tid] ? 0.0f : 1e9f;
        if (tid < DD / 4)
            ((float4*)k0s)[tid] = ((const float4*)(k + (size_t)b * SK * DD))[tid];
    }

    // qn[qq][i]: negated dims [16c, 16c+16) of query qq, packed f32x2
    ull qn[4][8];
#pragma unroll
    for (int qq = 0; qq < 4; qq++) {
        const float* qrow = q + ((size_t)b * SQ + qt * QPB + g + 32 * qq) * DD + 16 * c;
#pragma unroll
        for (int i = 0; i < 4; i++) {
            float4 t = ((const float4*)qrow)[i];
            float2 a = make_float2(-t.x, -t.y);
            float2 d = make_float2(-t.z, -t.w);
            qn[qq][2 * i]     = *(ull*)&a;
            qn[qq][2 * i + 1] = *(ull*)&d;
        }
    }
    __syncthreads();

    // reference distances dist0 (quarter -> hbuf -> join per thread)
    float d0l2[4];
    {
        const ull* kp = (const ull*)(k0s + 16 * c);
        ull kr[8];
#pragma unroll
        for (int i = 0; i < 8; i++) kr[i] = kp[i];
        float4 hq;
        float* hqp = (float*)&hq;
#pragma unroll
        for (int qq = 0; qq < 4; qq++) {
            ull s0 = add_f32x2(kr[0], qn[qq][0]) & ABS2_MASK;
            ull s1 = add_f32x2(kr[1], qn[qq][1]) & ABS2_MASK;
#pragma unroll
            for (int i = 2; i < 8; i += 2) {
                s0 = add_f32x2(s0, add_f32x2(kr[i],     qn[qq][i])     & ABS2_MASK);
                s1 = add_f32x2(s1, add_f32x2(kr[i + 1], qn[qq][i + 1]) & ABS2_MASK);
            }
            s0 = add_f32x2(s0, s1);
            float2 f = *(float2*)&s0;
            hqp[qq] = f.x + f.y;
        }
        hbuf[0][c][g] = hq;
        __syncthreads();
        float4 h0 = hbuf[0][0][g];
        float4 h1 = hbuf[0][1][g];
        float4 h2 = hbuf[0][2][g];
        float4 h3 = hbuf[0][3][g];
        d0l2[0] = (h0.x + h1.x + h2.x + h3.x) * LOG2E;
        d0l2[1] = (h0.y + h1.y + h2.y + h3.y) * LOG2E;
        d0l2[2] = (h0.z + h1.z + h2.z + h3.z) * LOG2E;
        d0l2[3] = (h0.w + h1.w + h2.w + h3.w) * LOG2E;
        __syncthreads();
    }

    ull acc[4][8];
#pragma unroll
    for (int qq = 0; qq < 4; qq++)
#pragma unroll
        for (int i = 0; i < 8; i++) acc[qq][i] = 0ULL;
    ull lsA = 0ULL, lsB = 0ULL;   // packed lsum for (q0,q1),(q2,q3)

#pragma unroll 1
    for (int jb = 0; jb < KCHUNK; jb += KB) {
        // phase 1a: quarter distances for KB keys x 4 queries
#pragma unroll 4
        for (int j = 0; j < KB; j++) {
            const ull* kp = (const ull*)(&ks[jb + j][16 * c]);
            ull kr[8];
#pragma unroll
            for (int i = 0; i < 8; i++) kr[i] = kp[i];
            float4 hq;
            float* hqp = (float*)&hq;
#pragma unroll
            for (int qq = 0; qq < 4; qq++) {
                ull s0 = add_f32x2(kr[0], qn[qq][0]) & ABS2_MASK;
                ull s1 = add_f32x2(kr[1], qn[qq][1]) & ABS2_MASK;
#pragma unroll
                for (int i = 2; i < 8; i += 2) {
                    s0 = add_f32x2(s0, add_f32x2(kr[i],     qn[qq][i])     & ABS2_MASK);
                    s1 = add_f32x2(s1, add_f32x2(kr[i + 1], qn[qq][i + 1]) & ABS2_MASK);
                }
                s0 = add_f32x2(s0, s1);
                float2 f = *(float2*)&s0;
                hqp[qq] = f.x + f.y;
            }
            hbuf[j][c][g] = hq;
        }
        __syncthreads();

        // phase 1b: join quarters + softmax numerator; 2 tasks per thread
#pragma unroll
        for (int t = 0; t < 2; t++) {
            int j = c + 4 * t;
            float4 h0 = hbuf[j][0][g];
            float4 h1 = hbuf[j][1][g];
            float4 h2 = hbuf[j][2][g];
            float4 h3 = hbuf[j][3][g];
            float bj = bias[jb + j];
            float4 p;
            p.x = ex2(fmaf(h0.x + h1.x + h2.x + h3.x + bj, -LOG2E, d0l2[0]));
            p.y = ex2(fmaf(h0.y + h1.y + h2.y + h3.y + bj, -LOG2E, d0l2[1]));
            p.z = ex2(fmaf(h0.z + h1.z + h2.z + h3.z + bj, -LOG2E, d0l2[2]));
            p.w = ex2(fmaf(h0.w + h1.w + h2.w + h3.w + bj, -LOG2E, d0l2[3]));
            hbuf[j][0][g] = p;
        }
        __syncthreads();

        // phase 2: AV accumulation
#pragma unroll 4
        for (int j = 0; j < KB; j++) {
            float4 p4 = hbuf[j][0][g];
            const ull* vp = (const ull*)(&vs[jb + j][16 * c]);
            ull vr[8];
#pragma unroll
            for (int i = 0; i < 8; i++) vr[i] = vp[i];
            lsA = add_f32x2(lsA, *(ull*)&p4.x);
            lsB = add_f32x2(lsB, *(ull*)&p4.z);
            const float* pf = (const float*)&p4;
#pragma unroll
            for (int qq = 0; qq < 4; qq++) {
                ull pp = pack_dup(pf[qq]);
#pragma unroll
                for (int i = 0; i < 8; i++)
                    acc[qq][i] = fma_f32x2(vr[i], pp, acc[qq][i]);
            }
        }
        __syncthreads();
    }

    // store partials: dp slice [8c, 8c+8) for 4 queries; coalesced STG.64
    {
        ull* pb = g_pacc + ((size_t)(b * NSPLIT + sg) * (DV / 2)) * SQ;
#pragma unroll
        for (int qq = 0; qq < 4; qq++) {
            int qi = qt * QPB + g + 32 * qq;
#pragma unroll
            for (int i = 0; i < 8; i++)
                pb[(size_t)(8 * c + i) * SQ + qi] = acc[qq][i];
        }
        if (c == 0) {
            float2 la = *(float2*)&lsA;
            float2 lb2 = *(float2*)&lsB;
            float* plb = g_pl + (size_t)(b * NSPLIT + sg) * SQ + qt * QPB + g;
            plb[0]  = la.x;
            plb[32] = la.y;
            plb[64] = lb2.x;
            plb[96] = lb2.y;
        }
    }

    // ---- arrival ticket: last NTAIL blocks per (b, qtile) combine ----
    const int tile = b * NTILE + qt;
    __threadfence();
    __syncthreads();
    if (tid == 0) rank_s = atomicAdd(&g_cnt[tile], 1);
    __syncthreads();
    const int rk = rank_s;
    if (rk < NSPLIT - NTAIL) return;

    if (tid == 0) {
        while (*(volatile int*)&g_cnt[tile] < NSPLIT) { }
    }
    __syncthreads();
    __threadfence();

    const int r = rk - (NSPLIT - NTAIL);     // 0..3 -> dp slice [8r, 8r+8)
    const int qi = qt * QPB + tid;           // thread = query

    float lt = 0.0f;
#pragma unroll
    for (int s2 = 0; s2 < NSPLIT; s2++)
        lt += g_pl[(size_t)(b * NSPLIT + s2) * SQ + qi];
    const float li = 1.0f / lt;

    ull a[8];
#pragma unroll
    for (int i = 0; i < 8; i++) a[i] = 0ULL;
#pragma unroll
    for (int s2 = 0; s2 < NSPLIT; s2++) {
        const ull* base = g_pacc +
            ((size_t)(b * NSPLIT + s2) * (DV / 2) + 8 * r) * SQ + qi;
#pragma unroll
        for (int i = 0; i < 8; i++)
            a[i] = add_f32x2(a[i], base[(size_t)i * SQ]);
    }
#pragma unroll
    for (int i = 0; i < 8; i++) {
        float2 f = *(float2*)&a[i];
        float2 rr = make_float2(f.x * li, f.y * li);
        *(float2*)&out[((size_t)b * SQ + qi) * DV + 2 * (8 * r + i)] = rr;
    }

    __threadfence();
    __syncthreads();
    if (tid == 0) {
        int f = atomicAdd(&g_fin[tile], 1);
        if (f == NTAIL - 1) {
            g_cnt[tile] = 0;
            g_fin[tile] = 0;
            __threadfence();
        }
    }
}

extern "C" void kernel_launch(void* const* d_in, const int* in_sizes, int n_in,
                              void* d_out, int out_size)
{
    const float* q    = (const float*)d_in[0];
    const float* k    = (const float*)d_in[1];
    const float* v    = (const float*)d_in[2];
    const int*   mask = (const int*)d_in[3];
    float* out = (float*)d_out;

    dim3 grid(NTILE, NSPLIT, BB);
    attn_fused<<<grid, TPB>>>(q, k, v, mask, out);
}

// round 6
// speedup vs baseline: 1.0913x; 1.0913x over previous
#include <cuda_runtime.h>
#include <cstdint>

#define BB 2
#define SQ 1024
#define SK 1024
#define DD 64
#define DV 64
#define NSPLIT 16
#define KCHUNK 64              // keys per block
#define QPB 64                 // queries per block (4 warps x 16)
#define TPB 128
#define NTILE (SQ / QPB)       // 16
#define NTAIL 4

#define LOG2E 1.4426950408889634f
#define ABS2_MASK 0x7FFFFFFF7FFFFFFFULL
#define FULLM 0xffffffffu

typedef unsigned long long ull;

// partials: [b][split][dp(32)][q(1024)]  (8MB, L2-resident)
__device__ ull   g_pacc[(size_t)BB * NSPLIT * (DV / 2) * SQ];
__device__ float g_pl[(size_t)BB * NSPLIT * SQ];
__device__ int   g_cnt[BB * NTILE];
__device__ int   g_fin[BB * NTILE];

__device__ __forceinline__ ull add_f32x2(ull a, ull b) {
    ull r;
    asm("add.rn.f32x2 %0, %1, %2;" : "=l"(r) : "l"(a), "l"(b));
    return r;
}
__device__ __forceinline__ ull fma_f32x2(ull a, ull b, ull c) {
    ull r;
    asm("fma.rn.f32x2 %0, %1, %2, %3;" : "=l"(r) : "l"(a), "l"(b), "l"(c));
    return r;
}
__device__ __forceinline__ ull pack_dup(float p) {
    ull r;
    asm("mov.b64 %0, {%1, %1};" : "=l"(r) : "r"(__float_as_uint(p)));
    return r;
}
__device__ __forceinline__ float ex2(float x) {
    float r;
    asm("ex2.approx.f32 %0, %1;" : "=f"(r) : "f"(x));
    return r;
}

// 8-dim partial L1 for one query: 4 packed diffs+abs, 3 packed adds, 1 scalar
__device__ __forceinline__ float l1_8(ull k0, ull k1, ull k2, ull k3,
                                      const ull* __restrict__ qn)
{
    ull t0 = add_f32x2(k0, qn[0]) & ABS2_MASK;
    ull t1 = add_f32x2(k1, qn[1]) & ABS2_MASK;
    ull t2 = add_f32x2(k2, qn[2]) & ABS2_MASK;
    ull t3 = add_f32x2(k3, qn[3]) & ABS2_MASK;
    t0 = add_f32x2(t0, t1);
    t2 = add_f32x2(t2, t3);
    t0 = add_f32x2(t0, t2);
    float2 f = *(float2*)&t0;
    return f.x + f.y;
}

__global__ __launch_bounds__(TPB, 4)
void attn_fused(const float* __restrict__ q, const float* __restrict__ k,
                const float* __restrict__ v, const int* __restrict__ mask,
                float* __restrict__ out)
{
    const int b   = blockIdx.z;
    const int sg  = blockIdx.y;           // split 0..15
    const int qt  = blockIdx.x;           // q tile 0..15
    const int tid = threadIdx.x;
    const int wid = tid >> 5;             // warp 0..3 -> 16 queries each
    const int ln  = tid & 31;
    const int c   = ln & 7;               // dim octet 0..7 -> dims [8c, 8c+8)
    const int qs  = ln >> 3;              // query slot 0..3
    // this thread's 4 queries: qt*64 + wid*16 + 4*qq + qs

    __shared__ __align__(16) float ks[KCHUNK][DD];   // 16KB
    __shared__ __align__(16) float vs[KCHUNK][DV];   // 16KB
    __shared__ __align__(16) float k0s[DD];
    __shared__ float bias[KCHUNK];
    __shared__ int   rank_s;

    // cooperative loads
    {
        const float* kb = k + ((size_t)b * SK + (size_t)sg * KCHUNK) * DD;
        const float* vb = v + ((size_t)b * SK + (size_t)sg * KCHUNK) * DV;
#pragma unroll
        for (int i = tid; i < KCHUNK * DD / 4; i += TPB) {
            ((float4*)&ks[0][0])[i] = ((const float4*)kb)[i];
            ((float4*)&vs[0][0])[i] = ((const float4*)vb)[i];
        }
        if (tid < KCHUNK)
            bias[tid] = mask[(size_t)b * SK + (size_t)sg * KCHUNK + tid] ? 0.0f : 1e9f;
        if (tid < DD / 4)
            ((float4*)k0s)[tid] = ((const float4*)(k + (size_t)b * SK * DD))[tid];
    }

    // qn[qq][0..3]: negated dims [8c, 8c+8) of query qq, packed f32x2 (32 regs)
    ull qn[4][4];
#pragma unroll
    for (int qq = 0; qq < 4; qq++) {
        const float* qrow =
            q + ((size_t)b * SQ + qt * QPB + wid * 16 + 4 * qq + qs) * DD + 8 * c;
#pragma unroll
        for (int i = 0; i < 2; i++) {
            float4 t = ((const float4*)qrow)[i];
            float2 a = make_float2(-t.x, -t.y);
            float2 d = make_float2(-t.z, -t.w);
            qn[qq][2 * i]     = *(ull*)&a;
            qn[qq][2 * i + 1] = *(ull*)&d;
        }
    }
    __syncthreads();

    // reference distances: butterfly-join octet partials within the warp
    float d0l2[4];
    {
        const ull* kp = (const ull*)(k0s + 8 * c);
        ull k0 = kp[0], k1 = kp[1], k2 = kp[2], k3 = kp[3];
#pragma unroll
        for (int qq = 0; qq < 4; qq++) {
            float d = l1_8(k0, k1, k2, k3, qn[qq]);
            d += __shfl_xor_sync(FULLM, d, 1);
            d += __shfl_xor_sync(FULLM, d, 2);
            d += __shfl_xor_sync(FULLM, d, 4);
            d0l2[qq] = d * LOG2E;
        }
    }

    ull acc[4][4];                        // 4 queries x dims [8c, 8c+8)  (32 regs)
#pragma unroll
    for (int qq = 0; qq < 4; qq++)
#pragma unroll
        for (int i = 0; i < 4; i++) acc[qq][i] = 0ULL;
    float lsum[4] = {0.0f, 0.0f, 0.0f, 0.0f};

#pragma unroll 2
    for (int j = 0; j < KCHUNK; j++) {
        const ull* kp = (const ull*)(&ks[j][8 * c]);
        ull k0 = kp[0], k1 = kp[1], k2 = kp[2], k3 = kp[3];

        float dp0 = l1_8(k0, k1, k2, k3, qn[0]);
        float dp1 = l1_8(k0, k1, k2, k3, qn[1]);
        float dp2 = l1_8(k0, k1, k2, k3, qn[2]);
        float dp3 = l1_8(k0, k1, k2, k3, qn[3]);

        dp0 += __shfl_xor_sync(FULLM, dp0, 1);
        dp1 += __shfl_xor_sync(FULLM, dp1, 1);
        dp2 += __shfl_xor_sync(FULLM, dp2, 1);
        dp3 += __shfl_xor_sync(FULLM, dp3, 1);
        dp0 += __shfl_xor_sync(FULLM, dp0, 2);
        dp1 += __shfl_xor_sync(FULLM, dp1, 2);
        dp2 += __shfl_xor_sync(FULLM, dp2, 2);
        dp3 += __shfl_xor_sync(FULLM, dp3, 2);
        dp0 += __shfl_xor_sync(FULLM, dp0, 4);
        dp1 += __shfl_xor_sync(FULLM, dp1, 4);
        dp2 += __shfl_xor_sync(FULLM, dp2, 4);
        dp3 += __shfl_xor_sync(FULLM, dp3, 4);

        const float bj = bias[j];
        float p0 = ex2(fmaf(dp0 + bj, -LOG2E, d0l2[0]));
        float p1 = ex2(fmaf(dp1 + bj, -LOG2E, d0l2[1]));
        float p2 = ex2(fmaf(dp2 + bj, -LOG2E, d0l2[2]));
        float p3 = ex2(fmaf(dp3 + bj, -LOG2E, d0l2[3]));
        lsum[0] += p0; lsum[1] += p1; lsum[2] += p2; lsum[3] += p3;

        const ull* vp = (const ull*)(&vs[j][8 * c]);
        ull v0 = vp[0], v1 = vp[1], v2 = vp[2], v3 = vp[3];
        ull pp;
        pp = pack_dup(p0);
        acc[0][0] = fma_f32x2(v0, pp, acc[0][0]);
        acc[0][1] = fma_f32x2(v1, pp, acc[0][1]);
        acc[0][2] = fma_f32x2(v2, pp, acc[0][2]);
        acc[0][3] = fma_f32x2(v3, pp, acc[0][3]);
        pp = pack_dup(p1);
        acc[1][0] = fma_f32x2(v0, pp, acc[1][0]);
        acc[1][1] = fma_f32x2(v1, pp, acc[1][1]);
        acc[1][2] = fma_f32x2(v2, pp, acc[1][2]);
        acc[1][3] = fma_f32x2(v3, pp, acc[1][3]);
        pp = pack_dup(p2);
        acc[2][0] = fma_f32x2(v0, pp, acc[2][0]);
        acc[2][1] = fma_f32x2(v1, pp, acc[2][1]);
        acc[2][2] = fma_f32x2(v2, pp, acc[2][2]);
        acc[2][3] = fma_f32x2(v3, pp, acc[2][3]);
        pp = pack_dup(p3);
        acc[3][0] = fma_f32x2(v0, pp, acc[3][0]);
        acc[3][1] = fma_f32x2(v1, pp, acc[3][1]);
        acc[3][2] = fma_f32x2(v2, pp, acc[3][2]);
        acc[3][3] = fma_f32x2(v3, pp, acc[3][3]);
    }

    // store partials: dp = 4c+i, queries in runs of 4 (coalesced 32B segments)
    {
        ull* pb = g_pacc + ((size_t)(b * NSPLIT + sg) * (DV / 2)) * SQ;
#pragma unroll
        for (int qq = 0; qq < 4; qq++) {
            const int qi = qt * QPB + wid * 16 + 4 * qq + qs;
#pragma unroll
            for (int i = 0; i < 4; i++)
                pb[(size_t)(4 * c + i) * SQ + qi] = acc[qq][i];
        }
        if (c == 0) {
            float* plb = g_pl + (size_t)(b * NSPLIT + sg) * SQ + qt * QPB + wid * 16 + qs;
#pragma unroll
            for (int qq = 0; qq < 4; qq++)
                plb[4 * qq] = lsum[qq];
        }
    }

    // ---- arrival ticket: last NTAIL blocks per (b, qtile) combine ----
    const int tile = b * NTILE + qt;
    __threadfence();
    __syncthreads();
    if (tid == 0) rank_s = atomicAdd(&g_cnt[tile], 1);
    __syncthreads();
    const int rk = rank_s;
    if (rk < NSPLIT - NTAIL) return;

    if (tid == 0) {
        while (*(volatile int*)&g_cnt[tile] < NSPLIT) { }
    }
    __syncthreads();
    __threadfence();

    const int r   = rk - (NSPLIT - NTAIL);   // 0..3
    const int ql  = tid & 63;
    const int dh  = tid >> 6;                // 0..1
    const int qi  = qt * QPB + ql;
    const int dpb = 8 * r + 4 * dh;          // 4 dp per thread

    float lt = 0.0f;
#pragma unroll
    for (int s2 = 0; s2 < NSPLIT; s2++)
        lt += g_pl[(size_t)(b * NSPLIT + s2) * SQ + qi];
    const float li = 1.0f / lt;

    ull a[4] = {0ULL, 0ULL, 0ULL, 0ULL};
#pragma unroll
    for (int s2 = 0; s2 < NSPLIT; s2++) {
        const ull* base =
            g_pacc + ((size_t)(b * NSPLIT + s2) * (DV / 2) + dpb) * SQ + qi;
#pragma unroll
        for (int i = 0; i < 4; i++)
            a[i] = add_f32x2(a[i], base[(size_t)i * SQ]);
    }
#pragma unroll
    for (int i = 0; i < 4; i++) {
        float2 f = *(float2*)&a[i];
        float2 rr = make_float2(f.x * li, f.y * li);
        *(float2*)&out[((size_t)b * SQ + qi) * DV + 2 * (dpb + i)] = rr;
    }

    __threadfence();
    __syncthreads();
    if (tid == 0) {
        int f = atomicAdd(&g_fin[tile], 1);
        if (f == NTAIL - 1) {
            g_cnt[tile] = 0;
            g_fin[tile] = 0;
            __threadfence();
        }
    }
}

extern "C" void kernel_launch(void* const* d_in, const int* in_sizes, int n_in,
                              void* d_out, int out_size)
{
    const float* q    = (const float*)d_in[0];
    const float* k    = (const float*)d_in[1];
    const float* v    = (const float*)d_in[2];
    const int*   mask = (const int*)d_in[3];
    float* out = (float*)d_out;

    dim3 grid(NTILE, NSPLIT, BB);
    attn_fused<<<grid, TPB>>>(q, k, v, mask, out);
}

// round 7
// speedup vs baseline: 1.1476x; 1.0516x over previous
#include <cuda_runtime.h>
#include <cstdint>

#define BB 2
#define SQ 1024
#define SK 1024
#define DD 64
#define DV 64
#define NSPLIT 16
#define KCHUNK 64              // keys per block, streamed in 2 stages of 32
#define KSTG 32                // keys per smem stage
#define QPB 32                 // queries per block (2 warps x 16)
#define TPB 64
#define NTILE (SQ / QPB)       // 32
#define NTAIL 4

#define LOG2E 1.4426950408889634f
#define ABS2_MASK 0x7FFFFFFF7FFFFFFFULL
#define FULLM 0xffffffffu

typedef unsigned long long ull;

// partials: [b][split][dp(32)][q(1024)]  (8MB, L2-resident)
__device__ ull   g_pacc[(size_t)BB * NSPLIT * (DV / 2) * SQ];
__device__ float g_pl[(size_t)BB * NSPLIT * SQ];
__device__ int   g_cnt[BB * NTILE];
__device__ int   g_fin[BB * NTILE];

__device__ __forceinline__ ull add_f32x2(ull a, ull b) {
    ull r;
    asm("add.rn.f32x2 %0, %1, %2;" : "=l"(r) : "l"(a), "l"(b));
    return r;
}
__device__ __forceinline__ ull fma_f32x2(ull a, ull b, ull c) {
    ull r;
    asm("fma.rn.f32x2 %0, %1, %2, %3;" : "=l"(r) : "l"(a), "l"(b), "l"(c));
    return r;
}
__device__ __forceinline__ ull pack_dup(float p) {
    ull r;
    asm("mov.b64 %0, {%1, %1};" : "=l"(r) : "r"(__float_as_uint(p)));
    return r;
}
__device__ __forceinline__ float ex2(float x) {
    float r;
    asm("ex2.approx.f32 %0, %1;" : "=f"(r) : "f"(x));
    return r;
}

// L1 distance over 32 dims: 8 LDS.128 (2 distinct addrs/warp -> broadcast),
// 16 packed diffs + abs, 4 accumulation chains.
__device__ __forceinline__ float l1_32(const ulonglong2* __restrict__ kp,
                                       const ull* __restrict__ qn)
{
    ulonglong2 ka = kp[0];
    ulonglong2 kb = kp[1];
    ull s0 = add_f32x2(ka.x, qn[0]) & ABS2_MASK;
    ull s1 = add_f32x2(ka.y, qn[1]) & ABS2_MASK;
    ull s2 = add_f32x2(kb.x, qn[2]) & ABS2_MASK;
    ull s3 = add_f32x2(kb.y, qn[3]) & ABS2_MASK;
#pragma unroll
    for (int i = 2; i < 8; i += 2) {
        ulonglong2 kc = kp[i];
        ulonglong2 kd = kp[i + 1];
        s0 = add_f32x2(s0, add_f32x2(kc.x, qn[2 * i])     & ABS2_MASK);
        s1 = add_f32x2(s1, add_f32x2(kc.y, qn[2 * i + 1]) & ABS2_MASK);
        s2 = add_f32x2(s2, add_f32x2(kd.x, qn[2 * i + 2]) & ABS2_MASK);
        s3 = add_f32x2(s3, add_f32x2(kd.y, qn[2 * i + 3]) & ABS2_MASK);
    }
    s0 = add_f32x2(s0, s2);
    s1 = add_f32x2(s1, s3);
    s0 = add_f32x2(s0, s1);
    float2 f = *(float2*)&s0;
    return f.x + f.y;
}

__global__ __launch_bounds__(TPB, 9)
void attn_fused(const float* __restrict__ q, const float* __restrict__ k,
                const float* __restrict__ v, const int* __restrict__ mask,
                float* __restrict__ out)
{
    const int b   = blockIdx.z;
    const int sg  = blockIdx.y;            // split 0..15
    const int qt  = blockIdx.x;            // q tile 0..31
    const int tid = threadIdx.x;
    const int wid = tid >> 5;              // warp 0/1
    const int ln  = tid & 31;
    const int s   = ln & 15;               // query slot 0..15
    const int h   = ln >> 4;               // dim half 0/1 -> dims [32h, 32h+32)
    const int qi  = qt * QPB + wid * 16 + s;

    __shared__ __align__(16) float ks[KSTG][DD];     // 8KB (reused per stage)
    __shared__ __align__(16) float vs[KSTG][DV];     // 8KB
    __shared__ __align__(16) float k0s[DD];
    __shared__ float bias[KCHUNK];
    __shared__ int   rank_s;

    // one-time loads: mask bias for all 64 keys + reference row k0
    if (tid < KCHUNK)
        bias[tid] = mask[(size_t)b * SK + (size_t)sg * KCHUNK + tid] ? 0.0f : 1e9f;
    if (tid < DD / 4)
        ((float4*)k0s)[tid] = ((const float4*)(k + (size_t)b * SK * DD))[tid];

    // this thread's negated q half (dims [32h, 32h+32)), packed f32x2: 16 ull
    ull qn[16];
    {
        const float* qrow = q + ((size_t)b * SQ + qi) * DD + 32 * h;
#pragma unroll
        for (int i = 0; i < 8; i++) {
            float4 t = ((const float4*)qrow)[i];
            float2 a = make_float2(-t.x, -t.y);
            float2 d = make_float2(-t.z, -t.w);
            qn[2 * i]     = *(ull*)&a;
            qn[2 * i + 1] = *(ull*)&d;
        }
    }
    __syncthreads();

    // reference distance: half + one butterfly join
    float d0l2;
    {
        float dh = l1_32((const ulonglong2*)(k0s + 32 * h), qn);
        dh += __shfl_xor_sync(FULLM, dh, 16);
        d0l2 = dh * LOG2E;
    }

    ull acc[16];                 // dims [32h, 32h+32) accumulators
#pragma unroll
    for (int i = 0; i < 16; i++) acc[i] = 0ULL;
    float lsum = 0.0f;

#pragma unroll 1
    for (int st = 0; st < KCHUNK / KSTG; st++) {
        if (st) __syncthreads();     // everyone done with previous stage smem
        // cooperative stage load: 32 keys of K and V (L2-hot)
        {
            const float* kb = k + ((size_t)b * SK + (size_t)sg * KCHUNK + st * KSTG) * DD;
            const float* vb = v + ((size_t)b * SK + (size_t)sg * KCHUNK + st * KSTG) * DV;
#pragma unroll
            for (int i = tid; i < KSTG * DD / 4; i += TPB) {
                ((float4*)&ks[0][0])[i] = ((const float4*)kb)[i];
                ((float4*)&vs[0][0])[i] = ((const float4*)vb)[i];
            }
        }
        __syncthreads();

#pragma unroll 2
        for (int j = 0; j < KSTG; j++) {
            float dh = l1_32((const ulonglong2*)(&ks[j][32 * h]), qn);
            dh += __shfl_xor_sync(FULLM, dh, 16);
            float p = ex2(fmaf(dh + bias[st * KSTG + j], -LOG2E, d0l2));
            lsum += p;
            ull pp = pack_dup(p);

            const ulonglong2* vp = (const ulonglong2*)(&vs[j][32 * h]);
#pragma unroll
            for (int i = 0; i < 8; i++) {
                ulonglong2 vv = vp[i];
                acc[2 * i]     = fma_f32x2(vv.x, pp, acc[2 * i]);
                acc[2 * i + 1] = fma_f32x2(vv.y, pp, acc[2 * i + 1]);
            }
        }
    }

    // store partials: dp = 16h + i at query qi (16-lane coalesced runs)
    {
        ull* pb = g_pacc + ((size_t)(b * NSPLIT + sg) * (DV / 2)) * SQ;
#pragma unroll
        for (int i = 0; i < 16; i++)
            pb[(size_t)(16 * h + i) * SQ + qi] = acc[i];
        if (h == 0)
            g_pl[(size_t)(b * NSPLIT + sg) * SQ + qi] = lsum;
    }

    // ---- arrival ticket: last NTAIL blocks per (b, qtile) combine ----
    const int tile = b * NTILE + qt;
    __threadfence();
    __syncthreads();
    if (tid == 0) rank_s = atomicAdd(&g_cnt[tile], 1);
    __syncthreads();
    const int rk = rank_s;
    if (rk < NSPLIT - NTAIL) return;

    if (tid == 0) {
        while (*(volatile int*)&g_cnt[tile] < NSPLIT) { }
    }
    __syncthreads();
    __threadfence();

    const int r   = rk - (NSPLIT - NTAIL);   // 0..3 -> dp slice [8r, 8r+8)
    const int ql  = tid & 31;
    const int dh2 = tid >> 5;                // 0..1
    const int qi2 = qt * QPB + ql;
    const int dpb = 8 * r + 4 * dh2;         // 4 dp per thread

    float lt = 0.0f;
#pragma unroll
    for (int s2 = 0; s2 < NSPLIT; s2++)
        lt += g_pl[(size_t)(b * NSPLIT + s2) * SQ + qi2];
    const float li = 1.0f / lt;

    ull a[4] = {0ULL, 0ULL, 0ULL, 0ULL};
#pragma unroll
    for (int s2 = 0; s2 < NSPLIT; s2++) {
        const ull* base =
            g_pacc + ((size_t)(b * NSPLIT + s2) * (DV / 2) + dpb) * SQ + qi2;
#pragma unroll
        for (int i = 0; i < 4; i++)
            a[i] = add_f32x2(a[i], base[(size_t)i * SQ]);
    }
#pragma unroll
    for (int i = 0; i < 4; i++) {
        float2 f = *(float2*)&a[i];
        float2 rr = make_float2(f.x * li, f.y * li);
        *(float2*)&out[((size_t)b * SQ + qi2) * DV + 2 * (dpb + i)] = rr;
    }

    __threadfence();
    __syncthreads();
    if (tid == 0) {
        int f = atomicAdd(&g_fin[tile], 1);
        if (f == NTAIL - 1) {
            g_cnt[tile] = 0;
            g_fin[tile] = 0;
            __threadfence();
        }
    }
}

extern "C" void kernel_launch(void* const* d_in, const int* in_sizes, int n_in,
                              void* d_out, int out_size)
{
    const float* q    = (const float*)d_in[0];
    const float* k    = (const float*)d_in[1];
    const float* v    = (const float*)d_in[2];
    const int*   mask = (const int*)d_in[3];
    float* out = (float*)d_out;

    dim3 grid(NTILE, NSPLIT, BB);
    attn_fused<<<grid, TPB>>>(q, k, v, mask, out);
}